// round 4
// baseline (speedup 1.0000x reference)
#include <cuda_runtime.h>

#define B_SZ 32
#define S_LEN 2048
#define D_MODEL 1024
#define NSTATE 256
#define LN_EPS 1e-5f

__device__ float g_u[B_SZ * S_LEN];
__device__ float g_s[B_SZ * S_LEN];

__device__ __forceinline__ float warp_sum(float v) {
    #pragma unroll
    for (int o = 16; o; o >>= 1) v += __shfl_xor_sync(0xffffffffu, v, o);
    return v;
}

// Kernel 1: u[b,s] = mean_k x[b,s,k].  One warp per row of 1024.
__global__ void mean_kernel(const float* __restrict__ x) {
    int gwarp = (blockIdx.x * blockDim.x + threadIdx.x) >> 5;  // row id, 65536 rows
    int lane  = threadIdx.x & 31;
    const float4* xp = (const float4*)(x + (size_t)gwarp * D_MODEL);
    float s = 0.f;
    #pragma unroll
    for (int k = 0; k < 8; k++) {
        float4 v = xp[lane + 32 * k];
        s += (v.x + v.y) + (v.z + v.w);
    }
    s = warp_sum(s);
    if (lane == 0) g_u[gwarp] = s * (1.0f / (float)D_MODEL);
}

// Kernel 2: sequential scan, one warp (one block of 32 threads) per batch.
// 8 states per lane. Recurrence:
//   z_{t+1}[i] = rs_t*(z_t[i]-mu_t)*(a*gamma)[i] + (a*beta)[i] + bd[i]*u_{t+1}
//   s_t        = rs_t*(sum(z_t*gamma*c) - mu_t*sum(gamma*c)) + sum(beta*c)
__global__ void scan_kernel(const float* __restrict__ llr,
                            const float* __restrict__ logb,
                            const float* __restrict__ cvec,
                            const float* __restrict__ logstep,
                            const float* __restrict__ lngamma,
                            const float* __restrict__ lnbeta) {
    __shared__ float su[S_LEN];
    __shared__ float ss[S_LEN];
    const int b = blockIdx.x;
    const int lane = threadIdx.x;

    // Stage this batch's u row into SMEM.
    {
        const float4* up = (const float4*)(g_u + (size_t)b * S_LEN);
        float4* sp = (float4*)su;
        #pragma unroll
        for (int k = 0; k < 16; k++) sp[lane + 32 * k] = up[lane + 32 * k];
    }

    const float step = expf(logstep[0]);
    float ag[8], ab_[8], bd[8], gc[8], z[8];
    float pgc = 0.f, pbc = 0.f;
    #pragma unroll
    for (int j = 0; j < 8; j++) {
        int i = lane + 32 * j;
        float lam = -expf(llr[i]);
        float a   = (2.0f + step * lam) / (2.0f - step * lam);
        float bb  = expf(logb[i]);
        bd[j] = step * (1.0f + a) * bb * 0.5f;
        float g  = lngamma[i];
        float be = lnbeta[i];
        float cc = cvec[i];
        ag[j]  = a * g;
        ab_[j] = a * be;
        gc[j]  = g * cc;
        pgc += g * cc;
        pbc += be * cc;
    }
    const float Sgc = warp_sum(pgc);
    const float Sbc = warp_sum(pbc);

    __syncwarp();
    // t = 0: h0 = 0 -> z0 = bd * u0
    {
        float u0 = su[0];
        #pragma unroll
        for (int j = 0; j < 8; j++) z[j] = bd[j] * u0;
    }

    const float invn = 1.0f / (float)NSTATE;
    for (int t = 0; t < S_LEN; t++) {
        // partial sums (pairwise trees)
        float q[8], m[8];
        #pragma unroll
        for (int j = 0; j < 8; j++) { q[j] = z[j] * z[j]; m[j] = z[j] * gc[j]; }
        float p1 = ((z[0] + z[1]) + (z[2] + z[3])) + ((z[4] + z[5]) + (z[6] + z[7]));
        float p2 = ((q[0] + q[1]) + (q[2] + q[3])) + ((q[4] + q[5]) + (q[6] + q[7]));
        float p3 = ((m[0] + m[1]) + (m[2] + m[3])) + ((m[4] + m[5]) + (m[6] + m[7]));

        // three interleaved butterflies (independent -> latency overlaps)
        #pragma unroll
        for (int o = 16; o; o >>= 1) {
            p1 += __shfl_xor_sync(0xffffffffu, p1, o);
            p2 += __shfl_xor_sync(0xffffffffu, p2, o);
            p3 += __shfl_xor_sync(0xffffffffu, p3, o);
        }

        float mu  = p1 * invn;
        float var = fmaf(p2, invn, -mu * mu);
        float rs  = rsqrtf(var + LN_EPS);

        if (lane == 0) ss[t] = fmaf(rs, fmaf(-mu, Sgc, p3), Sbc);

        if (t + 1 < S_LEN) {
            float un = su[t + 1];
            #pragma unroll
            for (int j = 0; j < 8; j++) {
                float cst = fmaf(bd[j], un, ab_[j]);
                z[j] = fmaf((z[j] - mu) * rs, ag[j], cst);
            }
        }
    }

    __syncwarp();
    {
        float4* gp = (float4*)(g_s + (size_t)b * S_LEN);
        const float4* sp = (const float4*)ss;
        #pragma unroll
        for (int k = 0; k < 16; k++) gp[lane + 32 * k] = sp[lane + 32 * k];
    }
}

// Kernel 3: out[b,s,:] = c1 * x[b,s,:] + c2 * s[b,s]
// with c1 = sig(alpha) + (1-sig(alpha))*d, c2 = (1-sig(alpha)).
__global__ void out_kernel(const float* __restrict__ x,
                           const float* __restrict__ alpha,
                           const float* __restrict__ logd,
                           float* __restrict__ out) {
    const int row = blockIdx.x;      // 65536 rows
    const int tid = threadIdx.x;     // 256 threads, one float4 each
    float a_sig = 1.0f / (1.0f + expf(-alpha[0]));
    float dd = expf(logd[0]);
    float c1 = a_sig + (1.0f - a_sig) * dd;
    float c2s = (1.0f - a_sig) * g_s[row];

    const float4* xp = (const float4*)(x + (size_t)row * D_MODEL);
    float4* op = (float4*)(out + (size_t)row * D_MODEL);
    float4 v = xp[tid];
    v.x = fmaf(c1, v.x, c2s);
    v.y = fmaf(c1, v.y, c2s);
    v.z = fmaf(c1, v.z, c2s);
    v.w = fmaf(c1, v.w, c2s);
    op[tid] = v;
}

extern "C" void kernel_launch(void* const* d_in, const int* in_sizes, int n_in,
                              void* d_out, int out_size) {
    const float* x        = (const float*)d_in[0];
    const float* llr      = (const float*)d_in[1];
    const float* logb     = (const float*)d_in[2];
    const float* cvec     = (const float*)d_in[3];
    const float* logd     = (const float*)d_in[4];
    const float* logstep  = (const float*)d_in[5];
    const float* alpha    = (const float*)d_in[6];
    const float* lngamma  = (const float*)d_in[7];
    const float* lnbeta   = (const float*)d_in[8];
    float* out = (float*)d_out;

    // rows = B*S = 65536; mean kernel: 8 warps per block
    mean_kernel<<<(B_SZ * S_LEN) / 8, 256>>>(x);
    scan_kernel<<<B_SZ, 32>>>(llr, logb, cvec, logstep, lngamma, lnbeta);
    out_kernel<<<B_SZ * S_LEN, 256>>>(x, alpha, logd, out);
}